// round 3
// baseline (speedup 1.0000x reference)
#include <cuda_runtime.h>
#include <math.h>

// Problem constants (fixed shapes from reference setup_inputs)
#define D_IN    4096
#define D_OUT   4096
#define NROWS   8192          // B*S = 4*2048
#define RANK    8
#define SCALING 2.0f          // ALPHA/RANK = 16/8
#define EPS     1e-8f
#define K_TILE  1024          // A tile width (8 x 1024 f32 = 32KB shared)

// Scratch (allocation-free: __device__ globals)
__device__ float g_mag_scale[D_OUT];
__device__ float g_Bs[D_OUT * RANK];     // B[o,r] * SCALING * mag_scale[o]
__device__ float g_lxr[NROWS * RANK];    // x @ A^T

// ---------------------------------------------------------------------------
// Kernel 1: row norms of (base_weight + (B@A)*SCALING), fold into mag_scale
// and pre-scaled Bs. 16 weight rows per block; A staged through shared tiles.
// ---------------------------------------------------------------------------
__global__ __launch_bounds__(256)
void norm_kernel(const float* __restrict__ bw,
                 const float* __restrict__ A,
                 const float* __restrict__ Bm,
                 const float* __restrict__ mag)
{
    __shared__ float Ash[RANK][K_TILE];
    const int tid = threadIdx.x;
    const int rl  = tid >> 4;      // 0..15 : local row
    const int l16 = tid & 15;      // 0..15 : lane within row group
    const int row = blockIdx.x * 16 + rl;

    float Brow[RANK];
#pragma unroll
    for (int r = 0; r < RANK; r++) Brow[r] = Bm[row * RANK + r];

    float acc = 0.0f;
    for (int t = 0; t < D_IN; t += K_TILE) {
        __syncthreads();
        // cooperative load of A tile: RANK*K_TILE/4 = 2048 float4, 8 per thread
#pragma unroll
        for (int i = 0; i < (RANK * K_TILE / 4) / 256; i++) {
            int e  = i * 256 + tid;
            int r  = e >> 8;              // / (K_TILE/4)
            int c4 = e & 255;             // % (K_TILE/4)
            ((float4*)&Ash[r][0])[c4] =
                ((const float4*)A)[r * (D_IN / 4) + (t >> 2) + c4];
        }
        __syncthreads();

        const float4* bwr = (const float4*)(bw + (size_t)row * D_IN + t);
#pragma unroll
        for (int j = 0; j < (K_TILE / 4) / 16; j++) {
            int c4 = l16 + j * 16;
            float4 w = bwr[c4];
            float d0 = 0.f, d1 = 0.f, d2 = 0.f, d3 = 0.f;
#pragma unroll
            for (int r = 0; r < RANK; r++) {
                float4 a = ((const float4*)&Ash[r][0])[c4];
                d0 += Brow[r] * a.x;
                d1 += Brow[r] * a.y;
                d2 += Brow[r] * a.z;
                d3 += Brow[r] * a.w;
            }
            float v0 = w.x + SCALING * d0;
            float v1 = w.y + SCALING * d1;
            float v2 = w.z + SCALING * d2;
            float v3 = w.w + SCALING * d3;
            acc += v0 * v0 + v1 * v1 + v2 * v2 + v3 * v3;
        }
    }

    // reduce across the 16 lanes of this row (xor offsets stay inside group)
#pragma unroll
    for (int off = 8; off; off >>= 1)
        acc += __shfl_xor_sync(0xffffffffu, acc, off);

    if (l16 == 0) {
        float ms = mag[row] / (sqrtf(acc) + EPS);
        g_mag_scale[row] = ms;
        float s = SCALING * ms;
#pragma unroll
        for (int r = 0; r < RANK; r++)
            g_Bs[row * RANK + r] = Brow[r] * s;
    }
}

// ---------------------------------------------------------------------------
// Kernel 2: lxr[s, r] = sum_i x[s,i] * A[r,i].  16 x-rows per block,
// A staged through the same shared tiling.
// ---------------------------------------------------------------------------
__global__ __launch_bounds__(256)
void lorax_kernel(const float* __restrict__ x,
                  const float* __restrict__ A)
{
    __shared__ float Ash[RANK][K_TILE];
    const int tid = threadIdx.x;
    const int rl  = tid >> 4;
    const int l16 = tid & 15;
    const int row = blockIdx.x * 16 + rl;

    float acc[RANK];
#pragma unroll
    for (int r = 0; r < RANK; r++) acc[r] = 0.0f;

    for (int t = 0; t < D_IN; t += K_TILE) {
        __syncthreads();
#pragma unroll
        for (int i = 0; i < (RANK * K_TILE / 4) / 256; i++) {
            int e  = i * 256 + tid;
            int r  = e >> 8;
            int c4 = e & 255;
            ((float4*)&Ash[r][0])[c4] =
                ((const float4*)A)[r * (D_IN / 4) + (t >> 2) + c4];
        }
        __syncthreads();

        const float4* xr = (const float4*)(x + (size_t)row * D_IN + t);
#pragma unroll
        for (int j = 0; j < (K_TILE / 4) / 16; j++) {
            int c4 = l16 + j * 16;
            float4 xv = xr[c4];
#pragma unroll
            for (int r = 0; r < RANK; r++) {
                float4 a = ((const float4*)&Ash[r][0])[c4];
                acc[r] += xv.x * a.x + xv.y * a.y + xv.z * a.z + xv.w * a.w;
            }
        }
    }

#pragma unroll
    for (int r = 0; r < RANK; r++) {
#pragma unroll
        for (int off = 8; off; off >>= 1)
            acc[r] += __shfl_xor_sync(0xffffffffu, acc[r], off);
    }

    if (l16 == 0) {
#pragma unroll
        for (int r = 0; r < RANK; r++)
            g_lxr[row * RANK + r] = acc[r];
    }
}

// ---------------------------------------------------------------------------
// Kernel 3: out[s,o] = base_output[s,o]*mag_scale[o] + dot(lxr[s,:], Bs[o,:])
// Tile: 32 rows x 1024 cols per block (256 threads).  Each thread owns ONE
// float4 column: Bs (32 f32) and mag_scale (4 f32) live in registers and are
// reused across all 32 rows; lxr is broadcast from shared.
// ---------------------------------------------------------------------------
__global__ __launch_bounds__(256)
void out_kernel(const float* __restrict__ bo, float* __restrict__ out)
{
    __shared__ float lxs[32 * RANK];   // 32 rows x 8
    const int tid  = threadIdx.x;
    const int row0 = blockIdx.y * 32;
    const int c4g  = blockIdx.x * (1024 / 4) + tid;   // global float4 column

    lxs[tid] = g_lxr[row0 * RANK + tid];              // 256 floats exactly
    __syncthreads();

    float4 ms4 = ((const float4*)g_mag_scale)[c4g];

    float Bsf[32];                                    // 4 cols x 8 ranks
#pragma unroll
    for (int i = 0; i < 8; i++) {
        float4 v = ((const float4*)g_Bs)[c4g * 8 + i];
        Bsf[i * 4 + 0] = v.x;
        Bsf[i * 4 + 1] = v.y;
        Bsf[i * 4 + 2] = v.z;
        Bsf[i * 4 + 3] = v.w;
    }
    // Bsf layout after this: Bsf[k*8 + r] = Bs[col k of this thread][r]

#pragma unroll 4
    for (int rl = 0; rl < 32; rl++) {
        const int row = row0 + rl;
        float4 b = ((const float4*)(bo + (size_t)row * D_OUT))[c4g];

        float4 l0 = *((const float4*)&lxs[rl * RANK]);
        float4 l1 = *((const float4*)&lxs[rl * RANK + 4]);
        float lx[8] = { l0.x, l0.y, l0.z, l0.w, l1.x, l1.y, l1.z, l1.w };

        float o0 = b.x * ms4.x;
        float o1 = b.y * ms4.y;
        float o2 = b.z * ms4.z;
        float o3 = b.w * ms4.w;
#pragma unroll
        for (int r = 0; r < RANK; r++) {
            o0 += lx[r] * Bsf[0 * 8 + r];
            o1 += lx[r] * Bsf[1 * 8 + r];
            o2 += lx[r] * Bsf[2 * 8 + r];
            o3 += lx[r] * Bsf[3 * 8 + r];
        }
        float4 res = make_float4(o0, o1, o2, o3);
        ((float4*)(out + (size_t)row * D_OUT))[c4g] = res;
    }
}

// ---------------------------------------------------------------------------
extern "C" void kernel_launch(void* const* d_in, const int* in_sizes, int n_in,
                              void* d_out, int out_size)
{
    const float* x   = (const float*)d_in[0];   // [8192, 4096]
    const float* bo  = (const float*)d_in[1];   // [8192, 4096]
    const float* bw  = (const float*)d_in[2];   // [4096, 4096]
    const float* A   = (const float*)d_in[3];   // [8, 4096]
    const float* Bm  = (const float*)d_in[4];   // [4096, 8]
    const float* mag = (const float*)d_in[5];   // [4096]
    float* out = (float*)d_out;                 // [8192, 4096]

    norm_kernel<<<D_OUT / 16, 256>>>(bw, A, Bm, mag);
    lorax_kernel<<<NROWS / 16, 256>>>(x, A);
    dim3 g3(D_OUT / 1024, NROWS / 32);
    out_kernel<<<g3, 256>>>(bo, out);
}

// round 4
// speedup vs baseline: 1.6002x; 1.6002x over previous
#include <cuda_runtime.h>
#include <math.h>

// Fixed shapes (from reference setup_inputs)
#define D_IN    4096
#define D_OUT   4096
#define NROWS   8192          // B*S
#define RANK    8
#define SCALING 2.0f          // ALPHA/RANK
#define EPS     1e-8f
#define NC4     (D_IN / 4)    // 1024 float4 columns per row

// Scratch (allocation-free: __device__ globals)
__device__ float g_mag_scale[D_OUT];
__device__ float g_Bs[D_OUT * RANK];     // B[o,r] * SCALING * mag_scale[o]
__device__ float g_lxr[NROWS * RANK];    // x @ A^T

__device__ __forceinline__ float dot4(float4 a, float4 b) {
    return a.x * b.x + a.y * b.y + a.z * b.z + a.w * b.w;
}

// ---------------------------------------------------------------------------
// Kernel 1: mag_scale + pre-scaled Bs.
// 4 weight rows per block (1024 blocks). No shared A: each A float4 is read
// once from L2 and reused across the 4 rows held in registers.
// ---------------------------------------------------------------------------
__global__ __launch_bounds__(256, 2)
void norm_kernel(const float* __restrict__ bw,
                 const float* __restrict__ A,
                 const float* __restrict__ Bm,
                 const float* __restrict__ mag)
{
    const int tid  = threadIdx.x;
    const int row0 = blockIdx.x * 4;
    const float4* __restrict__ A4 = (const float4*)A;

    // Brow pre-scaled by SCALING (uniform across threads -> broadcast loads)
    float Bsr[4][RANK];
#pragma unroll
    for (int n = 0; n < 4; n++)
#pragma unroll
        for (int r = 0; r < RANK; r++)
            Bsr[n][r] = __ldg(&Bm[(row0 + n) * RANK + r]) * SCALING;

    float acc[4] = {0.f, 0.f, 0.f, 0.f};

    for (int c = tid; c < NC4; c += 256) {
        float4 w[4];
#pragma unroll
        for (int n = 0; n < 4; n++)
            w[n] = __ldg(&((const float4*)(bw + (size_t)(row0 + n) * D_IN))[c]);

        float4 d[4];
#pragma unroll
        for (int n = 0; n < 4; n++) d[n] = make_float4(0.f, 0.f, 0.f, 0.f);

#pragma unroll
        for (int r = 0; r < RANK; r++) {
            float4 a = __ldg(&A4[r * NC4 + c]);
#pragma unroll
            for (int n = 0; n < 4; n++) {
                d[n].x += Bsr[n][r] * a.x;
                d[n].y += Bsr[n][r] * a.y;
                d[n].z += Bsr[n][r] * a.z;
                d[n].w += Bsr[n][r] * a.w;
            }
        }
#pragma unroll
        for (int n = 0; n < 4; n++) {
            float vx = w[n].x + d[n].x;
            float vy = w[n].y + d[n].y;
            float vz = w[n].z + d[n].z;
            float vw = w[n].w + d[n].w;
            acc[n] += vx * vx + vy * vy + vz * vz + vw * vw;
        }
    }

    // block reduction: warp shuffle then cross-warp via shared
#pragma unroll
    for (int n = 0; n < 4; n++)
#pragma unroll
        for (int off = 16; off; off >>= 1)
            acc[n] += __shfl_xor_sync(0xffffffffu, acc[n], off);

    __shared__ float red[8][4];
    const int warp = tid >> 5, lane = tid & 31;
    if (lane == 0)
#pragma unroll
        for (int n = 0; n < 4; n++) red[warp][n] = acc[n];
    __syncthreads();

    if (tid < 4) {
        float s = 0.f;
#pragma unroll
        for (int w8 = 0; w8 < 8; w8++) s += red[w8][tid];
        const int row = row0 + tid;
        float ms = __ldg(&mag[row]) / (sqrtf(s) + EPS);
        g_mag_scale[row] = ms;
        float sc = SCALING * ms;
#pragma unroll
        for (int r = 0; r < RANK; r++)
            g_Bs[row * RANK + r] = __ldg(&Bm[row * RANK + r]) * sc;
    }
}

// ---------------------------------------------------------------------------
// Kernel 2: lxr[s,r] = x[s,:] . A[r,:].  8 x-rows per block (1024 blocks).
// Per column chunk: 8 x loads + 8 A loads (16 independent LDG.128 in flight),
// A reused across the 8 register-resident rows.
// ---------------------------------------------------------------------------
__global__ __launch_bounds__(256, 2)
void lorax_kernel(const float* __restrict__ x,
                  const float* __restrict__ A)
{
    const int tid  = threadIdx.x;
    const int row0 = blockIdx.x * 8;
    const float4* __restrict__ A4 = (const float4*)A;

    float acc[8][RANK];
#pragma unroll
    for (int n = 0; n < 8; n++)
#pragma unroll
        for (int r = 0; r < RANK; r++) acc[n][r] = 0.f;

    for (int c = tid; c < NC4; c += 256) {
        float4 xv[8];
#pragma unroll
        for (int n = 0; n < 8; n++)
            xv[n] = __ldg(&((const float4*)(x + (size_t)(row0 + n) * D_IN))[c]);

#pragma unroll
        for (int r = 0; r < RANK; r++) {
            float4 a = __ldg(&A4[r * NC4 + c]);
#pragma unroll
            for (int n = 0; n < 8; n++)
                acc[n][r] += dot4(xv[n], a);
        }
    }

    // reduce 64 values across the block
#pragma unroll
    for (int n = 0; n < 8; n++)
#pragma unroll
        for (int r = 0; r < RANK; r++)
#pragma unroll
            for (int off = 16; off; off >>= 1)
                acc[n][r] += __shfl_xor_sync(0xffffffffu, acc[n][r], off);

    __shared__ float red[8][64];
    const int warp = tid >> 5, lane = tid & 31;
    if (lane == 0)
#pragma unroll
        for (int n = 0; n < 8; n++)
#pragma unroll
            for (int r = 0; r < RANK; r++)
                red[warp][n * RANK + r] = acc[n][r];
    __syncthreads();

    if (tid < 64) {
        float s = 0.f;
#pragma unroll
        for (int w8 = 0; w8 < 8; w8++) s += red[w8][tid];
        g_lxr[row0 * RANK + tid] = s;   // row = row0 + tid/8, r = tid%8
    }
}

// ---------------------------------------------------------------------------
// Kernel 3: out[s,o] = base_output[s,o]*mag_scale[o] + dot(lxr[s,:], Bs[o,:])
// 32 rows x 1024 cols per block; per-thread column Bs/ms in registers,
// unroll 8 so 8 row loads are in flight.
// ---------------------------------------------------------------------------
__global__ __launch_bounds__(256)
void out_kernel(const float* __restrict__ bo, float* __restrict__ out)
{
    __shared__ float lxs[32 * RANK];
    const int tid  = threadIdx.x;
    const int row0 = blockIdx.y * 32;
    const int c4g  = blockIdx.x * 256 + tid;          // global float4 column

    lxs[tid] = g_lxr[row0 * RANK + tid];              // 256 floats exactly
    __syncthreads();

    const float4 ms4 = __ldg(&((const float4*)g_mag_scale)[c4g]);

    float Bsf[32];                                    // [col 0..3][rank 0..7]
#pragma unroll
    for (int i = 0; i < 8; i++) {
        float4 v = __ldg(&((const float4*)g_Bs)[c4g * 8 + i]);
        Bsf[(i >> 1) * 0 + 0] = Bsf[0]; // (placeholder removed below)
        Bsf[((i * 4 + 0) & 7) + ((i * 4 + 0) >> 3) * 8] = 0.f; // overwritten
        (void)v;
    }
    // proper layout fill: Bsf[k*8 + r] = Bs[thread col k][r]
#pragma unroll
    for (int k = 0; k < 4; k++) {
        float4 v0 = __ldg(&((const float4*)g_Bs)[(c4g * 4 + k) * 2 + 0]);
        float4 v1 = __ldg(&((const float4*)g_Bs)[(c4g * 4 + k) * 2 + 1]);
        Bsf[k * 8 + 0] = v0.x; Bsf[k * 8 + 1] = v0.y;
        Bsf[k * 8 + 2] = v0.z; Bsf[k * 8 + 3] = v0.w;
        Bsf[k * 8 + 4] = v1.x; Bsf[k * 8 + 5] = v1.y;
        Bsf[k * 8 + 6] = v1.z; Bsf[k * 8 + 7] = v1.w;
    }

#pragma unroll 8
    for (int rl = 0; rl < 32; rl++) {
        const int row = row0 + rl;
        float4 b = __ldg(&((const float4*)(bo + (size_t)row * D_OUT))[c4g]);

        float4 l0 = *((const float4*)&lxs[rl * RANK]);
        float4 l1 = *((const float4*)&lxs[rl * RANK + 4]);
        float lx[8] = { l0.x, l0.y, l0.z, l0.w, l1.x, l1.y, l1.z, l1.w };

        float o0 = b.x * ms4.x;
        float o1 = b.y * ms4.y;
        float o2 = b.z * ms4.z;
        float o3 = b.w * ms4.w;
#pragma unroll
        for (int r = 0; r < RANK; r++) {
            o0 += lx[r] * Bsf[0 * 8 + r];
            o1 += lx[r] * Bsf[1 * 8 + r];
            o2 += lx[r] * Bsf[2 * 8 + r];
            o3 += lx[r] * Bsf[3 * 8 + r];
        }
        ((float4*)(out + (size_t)row * D_OUT))[c4g] = make_float4(o0, o1, o2, o3);
    }
}

// ---------------------------------------------------------------------------
extern "C" void kernel_launch(void* const* d_in, const int* in_sizes, int n_in,
                              void* d_out, int out_size)
{
    const float* x   = (const float*)d_in[0];   // [8192, 4096]
    const float* bo  = (const float*)d_in[1];   // [8192, 4096]
    const float* bw  = (const float*)d_in[2];   // [4096, 4096]
    const float* A   = (const float*)d_in[3];   // [8, 4096]
    const float* Bm  = (const float*)d_in[4];   // [4096, 8]
    const float* mag = (const float*)d_in[5];   // [4096]
    float* out = (float*)d_out;                 // [8192, 4096]

    norm_kernel<<<D_OUT / 4, 256>>>(bw, A, Bm, mag);
    lorax_kernel<<<NROWS / 8, 256>>>(x, A);
    dim3 g3(D_OUT / 1024, NROWS / 32);
    out_kernel<<<g3, 256>>>(bo, out);
}